// round 3
// baseline (speedup 1.0000x reference)
#include <cuda_runtime.h>
#include <math.h>

#define N_VEC  32768
#define DIM    256
#define KCODES 1024

#define BM 128
#define BN 128
#define BK 32
#define LDA 132   // padded smem row length (128 + 4) to dodge bank conflicts

#define OFF_QUANT  (N_VEC * DIM)                       // 8388608
#define OFF_ENC    (2 * N_VEC * DIM)                   // 16777216
#define OFF_QLOSS  (2 * N_VEC * DIM + N_VEC * KCODES)  // 50331648

__device__ float g_codeNorm[KCODES];
__device__ float g_rowNorm[N_VEC];
__device__ int   g_idx[N_VEC];
__device__ int   g_counts[KCODES];
__device__ float g_lossSum;

// ---------------------------------------------------------------------------
// Kernel 0a: per-code squared norms, XLA-GPU row-reduce order:
// lane-strided sequential FMA chain (i = 0..7) then shuffle tree.
// Block 0 also zeros the accumulators.
// ---------------------------------------------------------------------------
__global__ void vq_init(const float* __restrict__ w)
{
    const int warp = threadIdx.x >> 5;
    const int lane = threadIdx.x & 31;
    const int code = blockIdx.x * 8 + warp;

    const float* wr = w + (size_t)code * DIM;
    float s = 0.f;
#pragma unroll
    for (int i = 0; i < 8; i++) {
        float v = wr[lane + i * 32];
        s = fmaf(v, v, s);
    }
#pragma unroll
    for (int o = 16; o > 0; o >>= 1) s += __shfl_xor_sync(0xffffffffu, s, o);
    if (lane == 0) g_codeNorm[code] = s;

    if (blockIdx.x == 0) {
        for (int i = threadIdx.x; i < KCODES; i += 256) g_counts[i] = 0;
        if (threadIdx.x == 0) g_lossSum = 0.f;
    }
}

// ---------------------------------------------------------------------------
// Kernel 0b: per-row squared norms of the inputs, identical reduction order.
// ---------------------------------------------------------------------------
__global__ void vq_rownorm(const float* __restrict__ inp)
{
    const int warp = threadIdx.x >> 5;
    const int lane = threadIdx.x & 31;
    const int row  = blockIdx.x * 8 + warp;

    const float* xr = inp + (size_t)row * DIM;
    float s = 0.f;
#pragma unroll
    for (int i = 0; i < 8; i++) {
        float v = xr[lane + i * 32];
        s = fmaf(v, v, s);
    }
#pragma unroll
    for (int o = 16; o > 0; o >>= 1) s += __shfl_xor_sync(0xffffffffu, s, o);
    if (lane == 0) g_rowNorm[row] = s;
}

// ---------------------------------------------------------------------------
// Kernel 1: fused GEMM + argmin.
// Block = 256 threads (16x16), BM=128 rows resident in smem, K codes streamed
// in BN=128 chunks with BK=32 double-buffered stages. Per-accumulator dot is
// a strictly sequential k = 0..255 FFMA chain (cuBLAS sgemm order).
// Distance epilogue replicates the reference's fp32 rounding exactly:
//   dist = fl( fl(xnorm + enorm) - 2*dot )
// with first-index tie-breaking (jnp.argmin).
// ---------------------------------------------------------------------------
extern __shared__ float smem[];

__global__ void __launch_bounds__(256, 1)
vq_argmin(const float* __restrict__ inp, const float* __restrict__ wt)
{
    float* As = smem;                 // [DIM][LDA]  = 256*132 floats
    float* Bs = smem + DIM * LDA;     // [2][BK][LDA]

    const int tid = threadIdx.x;
    const int tx  = tid & 15;
    const int ty  = tid >> 4;
    const int rowBase = blockIdx.x * BM;

    // Load the A tile once, transposed to [d][row] for vectorized smem reads.
    for (int s = tid; s < BM * DIM / 4; s += 256) {
        int row = s >> 6;              // 64 float4 per row
        int dv  = s & 63;
        float4 v = __ldg((const float4*)(inp + (size_t)(rowBase + row) * DIM + dv * 4));
        int d = dv * 4;
        As[(d + 0) * LDA + row] = v.x;
        As[(d + 1) * LDA + row] = v.y;
        As[(d + 2) * LDA + row] = v.z;
        As[(d + 3) * LDA + row] = v.w;
    }

    // Per-thread row-norm registers (fixed row ownership across all chunks).
    float xnr[8];
#pragma unroll
    for (int i = 0; i < 8; i++) {
        int r = (i < 4) ? (ty * 4 + i) : (64 + ty * 4 + (i - 4));
        xnr[i] = g_rowNorm[rowBase + r];
    }

    float bestD[8];
    int   bestI[8];
#pragma unroll
    for (int i = 0; i < 8; i++) { bestD[i] = 3.4e38f; bestI[i] = 0; }

    float4 rB[4];

    for (int c = 0; c < KCODES / BN; c++) {
        const int colBase = c * BN;
        float acc[8][8];
#pragma unroll
        for (int i = 0; i < 8; i++)
#pragma unroll
            for (int j = 0; j < 8; j++) acc[i][j] = 0.f;

        // prefetch stage 0 of this chunk
#pragma unroll
        for (int i = 0; i < 4; i++) {
            int slot = tid + i * 256;          // 1024 float4 slots
            int col  = slot >> 3;
            int dv   = slot & 7;
            rB[i] = __ldg((const float4*)(wt + (size_t)(colBase + col) * DIM + dv * 4));
        }
        __syncthreads();   // previous chunk fully done with both buffers
        {
            float* B = Bs;
#pragma unroll
            for (int i = 0; i < 4; i++) {
                int slot = tid + i * 256;
                int col  = slot >> 3;
                int d    = (slot & 7) * 4;
                B[(d + 0) * LDA + col] = rB[i].x;
                B[(d + 1) * LDA + col] = rB[i].y;
                B[(d + 2) * LDA + col] = rB[i].z;
                B[(d + 3) * LDA + col] = rB[i].w;
            }
        }
        __syncthreads();

        for (int s = 0; s < DIM / BK; s++) {
            if (s < DIM / BK - 1) {
                const int d0n = (s + 1) * BK;
#pragma unroll
                for (int i = 0; i < 4; i++) {
                    int slot = tid + i * 256;
                    int col  = slot >> 3;
                    int dv   = slot & 7;
                    rB[i] = __ldg((const float4*)(wt + (size_t)(colBase + col) * DIM + d0n + dv * 4));
                }
            }
            const float* B  = Bs + (s & 1) * BK * LDA;
            const int    d0 = s * BK;
#pragma unroll
            for (int k = 0; k < BK; k++) {
                const float* Ak = As + (d0 + k) * LDA;
                float4 a0 = *(const float4*)(Ak + ty * 4);
                float4 a1 = *(const float4*)(Ak + 64 + ty * 4);
                const float* Bk = B + k * LDA;
                float4 b0 = *(const float4*)(Bk + tx * 4);
                float4 b1 = *(const float4*)(Bk + 64 + tx * 4);
                float a[8] = {a0.x, a0.y, a0.z, a0.w, a1.x, a1.y, a1.z, a1.w};
                float b[8] = {b0.x, b0.y, b0.z, b0.w, b1.x, b1.y, b1.z, b1.w};
#pragma unroll
                for (int i = 0; i < 8; i++)
#pragma unroll
                    for (int j = 0; j < 8; j++)
                        acc[i][j] = fmaf(a[i], b[j], acc[i][j]);
            }
            __syncthreads();
            if (s < DIM / BK - 1) {
                float* Bw = Bs + ((s + 1) & 1) * BK * LDA;
#pragma unroll
                for (int i = 0; i < 4; i++) {
                    int slot = tid + i * 256;
                    int col  = slot >> 3;
                    int d    = (slot & 7) * 4;
                    Bw[(d + 0) * LDA + col] = rB[i].x;
                    Bw[(d + 1) * LDA + col] = rB[i].y;
                    Bw[(d + 2) * LDA + col] = rB[i].z;
                    Bw[(d + 3) * LDA + col] = rB[i].w;
                }
                __syncthreads();
            }
        }

        // Reference-exact distances: dist = fl( fl(xn + en) - 2*dot ).
        // 2*dot is an exact power-of-two scaling; the two __fadd_rn round in
        // the reference's op order. Tie-break: lowest index.
#pragma unroll
        for (int j = 0; j < 8; j++) {
            int colL = (j < 4) ? (tx * 4 + j) : (64 + tx * 4 + (j - 4));
            int col  = colBase + colL;
            float cn = g_codeNorm[col];
#pragma unroll
            for (int i = 0; i < 8; i++) {
                float t1   = __fadd_rn(xnr[i], cn);
                float dist = __fadd_rn(t1, -2.0f * acc[i][j]);
                if (dist < bestD[i] || (dist == bestD[i] && col < bestI[i])) {
                    bestD[i] = dist;
                    bestI[i] = col;
                }
            }
        }
    }

    // cross-thread (tx) reduction per row; reuse As region
    __syncthreads();
    float* sMin = As;                       // 128*16 floats
    int*   sIdx = (int*)(As + BM * 16);     // 128*16 ints
#pragma unroll
    for (int i = 0; i < 8; i++) {
        int r = (i < 4) ? (ty * 4 + i) : (64 + ty * 4 + (i - 4));
        sMin[r * 16 + tx] = bestD[i];
        sIdx[r * 16 + tx] = bestI[i];
    }
    __syncthreads();
    if (tid < BM) {
        float bd = 3.4e38f;
        int   bi = 0x7fffffff;
        for (int t = 0; t < 16; t++) {
            float m  = sMin[tid * 16 + t];
            int   id = sIdx[tid * 16 + t];
            if (m < bd || (m == bd && id < bi)) { bd = m; bi = id; }
        }
        g_idx[rowBase + tid] = bi;
    }
}

// ---------------------------------------------------------------------------
// Kernel 2: one warp per row. Copies inputs, gathers the selected code,
// writes quantized_ste with the reference's exact rounding (x + (q - x)),
// writes the full one-hot row, accumulates squared-error sum + histogram.
// ---------------------------------------------------------------------------
__global__ void vq_quant(const float* __restrict__ inp, const float* __restrict__ wt,
                         float* __restrict__ out)
{
    __shared__ float bsum[8];
    const int warp = threadIdx.x >> 5;
    const int lane = threadIdx.x & 31;
    const int row  = blockIdx.x * 8 + warp;
    const int idx  = g_idx[row];

    const float4* x  = (const float4*)(inp + (size_t)row * DIM);
    const float4* w  = (const float4*)(wt + (size_t)idx * DIM);
    float4* oi = (float4*)(out + (size_t)row * DIM);
    float4* oq = (float4*)(out + OFF_QUANT + (size_t)row * DIM);
    float4* oe = (float4*)(out + OFF_ENC + (size_t)row * KCODES);

    float s = 0.f;
#pragma unroll
    for (int t = 0; t < 2; t++) {
        int p = lane + t * 32;
        float4 xv = __ldg(x + p);
        float4 wv = __ldg(w + p);
        oi[p] = xv;
        float4 qs;
        qs.x = __fadd_rn(xv.x, __fadd_rn(wv.x, -xv.x));
        qs.y = __fadd_rn(xv.y, __fadd_rn(wv.y, -xv.y));
        qs.z = __fadd_rn(xv.z, __fadd_rn(wv.z, -xv.z));
        qs.w = __fadd_rn(xv.w, __fadd_rn(wv.w, -xv.w));
        oq[p] = qs;
        float dx = wv.x - xv.x, dy = wv.y - xv.y;
        float dz = wv.z - xv.z, dw = wv.w - xv.w;
        s += dx * dx + dy * dy + dz * dz + dw * dw;
    }

    // one-hot row: 256 float4 per row, 8 per lane, coalesced
#pragma unroll
    for (int t = 0; t < 8; t++) {
        int p    = lane + t * 32;
        int base = p * 4;
        float4 v = make_float4(0.f, 0.f, 0.f, 0.f);
        int d = idx - base;
        if (d >= 0 && d < 4) {
            if (d == 0)      v.x = 1.f;
            else if (d == 1) v.y = 1.f;
            else if (d == 2) v.z = 1.f;
            else             v.w = 1.f;
        }
        oe[p] = v;
    }

#pragma unroll
    for (int o = 16; o > 0; o >>= 1) s += __shfl_xor_sync(0xffffffffu, s, o);
    if (lane == 0) {
        bsum[warp] = s;
        atomicAdd(&g_counts[idx], 1);
    }
    __syncthreads();
    if (threadIdx.x == 0) {
        float t = bsum[0] + bsum[1] + bsum[2] + bsum[3]
                + bsum[4] + bsum[5] + bsum[6] + bsum[7];
        atomicAdd(&g_lossSum, t);
    }
}

// ---------------------------------------------------------------------------
// Kernel 3: scalars — losses and perplexity.
// ---------------------------------------------------------------------------
__global__ void vq_final(float* __restrict__ out)
{
    __shared__ float red[1024];
    int t = threadIdx.x;
    float p = (float)g_counts[t] * (1.0f / (float)N_VEC);
    red[t] = p * logf(p + 1e-10f);
    __syncthreads();
    for (int o = 512; o > 0; o >>= 1) {
        if (t < o) red[t] += red[t + o];
        __syncthreads();
    }
    if (t == 0) {
        float loss = g_lossSum * (1.0f / (float)(N_VEC * DIM));
        out[OFF_QLOSS]     = loss;          // q_latent_loss
        out[OFF_QLOSS + 1] = loss;          // e_latent_loss
        out[OFF_QLOSS + 2] = expf(-red[0]); // perplexity
    }
}

// ---------------------------------------------------------------------------
extern "C" void kernel_launch(void* const* d_in, const int* in_sizes, int n_in,
                              void* d_out, int out_size)
{
    const float* inp = (const float*)d_in[0];
    const float* wt  = (const float*)d_in[1];
    if (n_in >= 2 && in_sizes[0] == KCODES * DIM && in_sizes[1] == N_VEC * DIM) {
        const float* tmp = inp; inp = wt; wt = tmp;
    }
    float* out = (float*)d_out;

    static bool attrDone = false;
    const size_t smemBytes = (size_t)(DIM * LDA + 2 * BK * LDA) * sizeof(float); // 168960
    if (!attrDone) {
        (void)cudaFuncSetAttribute(vq_argmin,
                                   cudaFuncAttributeMaxDynamicSharedMemorySize,
                                   (int)smemBytes);
        attrDone = true;
    }

    vq_init<<<KCODES / 8, 256>>>(wt);
    vq_rownorm<<<N_VEC / 8, 256>>>(inp);
    vq_argmin<<<N_VEC / BM, 256, smemBytes>>>(inp, wt);
    vq_quant<<<N_VEC / 8, 256>>>(inp, wt, out);
    vq_final<<<1, 1024>>>(out);
}

// round 5
// speedup vs baseline: 1.4934x; 1.4934x over previous
#include <cuda_runtime.h>
#include <math.h>
#include <stdint.h>

#define N_VEC  32768
#define DIM    256
#define KCODES 1024

#define OFF_QUANT  (N_VEC * DIM)
#define OFF_ENC    (2 * N_VEC * DIM)
#define OFF_QLOSS  (2 * N_VEC * DIM + N_VEC * KCODES)

#define THR 2e-4f

// mma tiling
#define BM 128
#define BN 128
#define BK 32
#define NCHUNKS (KCODES / BN)   // 8
#define LDAS 260                // A smem row stride (floats): banks 4g+tg distinct
#define LDBS 36                 // B smem col stride (floats): banks (4g+tg) distinct
#define LCAP 4096               // smem candidate list entries
#define FCAP 4608               // filtered list (reuses B smem)
#define GCAP (1 << 22)          // global candidate cap

// smem byte offsets
#define SO_A   0
#define SO_B   133120                    // 128*260*4
#define SO_CN  (SO_B + 18432)            // 128*36*4
#define SO_FB  (SO_CN + 4096)
#define SO_LD  (SO_FB + 512)
#define SO_LP  (SO_LD + LCAP * 4)
#define SO_CNT (SO_LP + LCAP * 4)
#define SM_TOTAL (SO_CNT + 64)           // ~189 KB

__device__ float g_codeNorm[KCODES];
__device__ float g_rowNorm[N_VEC];
__device__ unsigned long long g_key[N_VEC];
__device__ int   g_counts[KCODES];
__device__ float g_lossSum;
__device__ int   g_candCount;
__device__ unsigned int g_cand[GCAP];

// ---------------------------------------------------------------------------
__device__ __forceinline__ float tf32_rn(float x) {
    uint32_t u;
    asm("cvt.rna.tf32.f32 %0, %1;" : "=r"(u) : "f"(x));
    return __uint_as_float(u);
}

__device__ __forceinline__ void mma_tf32(float* c, const uint32_t* a,
                                         uint32_t b0, uint32_t b1) {
    asm volatile(
        "mma.sync.aligned.m16n8k8.row.col.f32.tf32.tf32.f32 "
        "{%0,%1,%2,%3}, {%4,%5,%6,%7}, {%8,%9}, {%0,%1,%2,%3};"
        : "+f"(c[0]), "+f"(c[1]), "+f"(c[2]), "+f"(c[3])
        : "r"(a[0]), "r"(a[1]), "r"(a[2]), "r"(a[3]), "r"(b0), "r"(b1));
}

// ---------------------------------------------------------------------------
__global__ void vq_init(const float* __restrict__ w)
{
    const int warp = threadIdx.x >> 5, lane = threadIdx.x & 31;
    const int code = blockIdx.x * 8 + warp;
    const float* wr = w + (size_t)code * DIM;
    float s = 0.f;
#pragma unroll
    for (int i = 0; i < 8; i++) { float v = wr[lane + i * 32]; s = fmaf(v, v, s); }
#pragma unroll
    for (int o = 16; o > 0; o >>= 1) s += __shfl_xor_sync(0xffffffffu, s, o);
    if (lane == 0) g_codeNorm[code] = s;
    if (blockIdx.x == 0) {
        for (int i = threadIdx.x; i < KCODES; i += 256) g_counts[i] = 0;
        if (threadIdx.x == 0) { g_lossSum = 0.f; g_candCount = 0; }
    }
}

__global__ void vq_rownorm(const float* __restrict__ inp)
{
    const int warp = threadIdx.x >> 5, lane = threadIdx.x & 31;
    const int row = blockIdx.x * 8 + warp;
    const float* xr = inp + (size_t)row * DIM;
    float s = 0.f;
#pragma unroll
    for (int i = 0; i < 8; i++) { float v = xr[lane + i * 32]; s = fmaf(v, v, s); }
#pragma unroll
    for (int o = 16; o > 0; o >>= 1) s += __shfl_xor_sync(0xffffffffu, s, o);
    if (lane == 0) { g_rowNorm[row] = s; g_key[row] = 0xFFFFFFFFFFFFFFFFull; }
}

// ---------------------------------------------------------------------------
extern __shared__ char dynsmem[];

__device__ __forceinline__ void candChk(float a, float xnv, float cn, float& best,
                                        int rl, int col, float* LD, unsigned* LP,
                                        int* s_cnt, int rowBase)
{
    float t = __fadd_rn(xnv, cn);
    float d = __fadd_rn(t, -2.0f * a);
    if (d <= best + THR) {
        if (d < best) best = d;
        int i = atomicAdd(s_cnt, 1);
        if (i < LCAP) { LD[i] = d; LP[i] = ((unsigned)rl << 10) | (unsigned)col; }
        else {
            int gi = atomicAdd(&g_candCount, 1);
            if (gi < GCAP)
                g_cand[gi] = ((unsigned)(rowBase + rl) << 10) | (unsigned)col;
        }
    }
}

__global__ void __launch_bounds__(256, 1)
vq_mma(const float* __restrict__ X, const float* __restrict__ W)
{
    float*    As  = (float*)(dynsmem + SO_A);
    float*    Bs  = (float*)(dynsmem + SO_B);
    float*    CNs = (float*)(dynsmem + SO_CN);
    float*    FBs = (float*)(dynsmem + SO_FB);
    float*    LD  = (float*)(dynsmem + SO_LD);
    unsigned* LP  = (unsigned*)(dynsmem + SO_LP);
    int*      s_cnt = (int*)(dynsmem + SO_CNT);
    int*      s_out = (int*)(dynsmem + SO_CNT + 4);
    int*      s_gb  = (int*)(dynsmem + SO_CNT + 8);
    unsigned* FL  = (unsigned*)Bs;   // reuse after mainloop

    const int tid = threadIdx.x;
    const int warp = tid >> 5, lane = tid & 31;
    const int wm = warp >> 1, wn = warp & 1;
    const int g = lane >> 2, tg = lane & 3;
    const int rowBase = blockIdx.x * BM;

    if (tid == 0) { *s_cnt = 0; *s_out = 0; }

    // A tile: load + tf32 convert, [row][k] stride LDAS
#pragma unroll
    for (int j = 0; j < 32; j++) {
        int l4 = tid + j * 256;
        int row = l4 >> 6, c4 = l4 & 63;
        float4 v = __ldg((const float4*)(X + (size_t)(rowBase + row) * DIM + c4 * 4));
        float4 t;
        t.x = tf32_rn(v.x); t.y = tf32_rn(v.y);
        t.z = tf32_rn(v.z); t.w = tf32_rn(v.w);
        *(float4*)(As + row * LDAS + c4 * 4) = t;
    }
#pragma unroll
    for (int j = 0; j < 4; j++) CNs[tid + j * 256] = g_codeNorm[tid + j * 256];

    float xn[4], best[4];
#pragma unroll
    for (int s = 0; s < 4; s++) {
        int rl = wm * 32 + (s >> 1) * 16 + (s & 1) * 8 + g;
        xn[s] = g_rowNorm[rowBase + rl];
        best[s] = 3.4e38f;
    }
    __syncthreads();

    for (int c = 0; c < NCHUNKS; c++) {
        const int colBase = c * BN;
        float acc[2][8][4];
#pragma unroll
        for (int mi = 0; mi < 2; mi++)
#pragma unroll
            for (int ni = 0; ni < 8; ni++)
#pragma unroll
                for (int q = 0; q < 4; q++) acc[mi][ni][q] = 0.f;

        float4 pre[4];
#pragma unroll
        for (int j = 0; j < 4; j++) {
            int lin = tid + j * 256;
            int col = lin >> 3, kq = lin & 7;
            pre[j] = __ldg((const float4*)(W + (size_t)(colBase + col) * DIM + kq * 4));
        }
        __syncthreads();   // Bs free (prev chunk finished)
#pragma unroll
        for (int j = 0; j < 4; j++) {
            int lin = tid + j * 256;
            int col = lin >> 3, kq = lin & 7;
            float4 v = pre[j], t;
            t.x = tf32_rn(v.x); t.y = tf32_rn(v.y);
            t.z = tf32_rn(v.z); t.w = tf32_rn(v.w);
            *(float4*)(Bs + col * LDBS + kq * 4) = t;
        }
        __syncthreads();

        for (int ks = 0; ks < DIM / BK; ks++) {
            if (ks < DIM / BK - 1) {
#pragma unroll
                for (int j = 0; j < 4; j++) {
                    int lin = tid + j * 256;
                    int col = lin >> 3, kq = lin & 7;
                    pre[j] = __ldg((const float4*)(W + (size_t)(colBase + col) * DIM
                                                   + (ks + 1) * BK + kq * 4));
                }
            }
#pragma unroll
            for (int k8 = 0; k8 < 4; k8++) {
                const int ka = ks * BK + k8 * 8 + tg;  // A global k
                const int kb = k8 * 8 + tg;            // B local k
                uint32_t aF[2][4];
#pragma unroll
                for (int mi = 0; mi < 2; mi++) {
                    const float* ap = As + (wm * 32 + mi * 16 + g) * LDAS;
                    aF[mi][0] = __float_as_uint(ap[ka]);
                    aF[mi][1] = __float_as_uint(ap[8 * LDAS + ka]);
                    aF[mi][2] = __float_as_uint(ap[ka + 4]);
                    aF[mi][3] = __float_as_uint(ap[8 * LDAS + ka + 4]);
                }
#pragma unroll
                for (int ni = 0; ni < 8; ni++) {
                    const float* bp = Bs + (wn * 64 + ni * 8 + g) * LDBS;
                    uint32_t b0 = __float_as_uint(bp[kb]);
                    uint32_t b1 = __float_as_uint(bp[kb + 4]);
                    mma_tf32(acc[0][ni], aF[0], b0, b1);
                    mma_tf32(acc[1][ni], aF[1], b0, b1);
                }
            }
            if (ks < DIM / BK - 1) {
                __syncthreads();
#pragma unroll
                for (int j = 0; j < 4; j++) {
                    int lin = tid + j * 256;
                    int col = lin >> 3, kq = lin & 7;
                    float4 v = pre[j], t;
                    t.x = tf32_rn(v.x); t.y = tf32_rn(v.y);
                    t.z = tf32_rn(v.z); t.w = tf32_rn(v.w);
                    *(float4*)(Bs + col * LDBS + kq * 4) = t;
                }
                __syncthreads();
            }
        }

        // distance epilogue + candidate appends
#pragma unroll
        for (int mi = 0; mi < 2; mi++) {
            const int rl0 = wm * 32 + mi * 16 + g;
            const int s0 = mi * 2, s1 = mi * 2 + 1;
#pragma unroll
            for (int ni = 0; ni < 8; ni++) {
                int col0 = colBase + wn * 64 + ni * 8 + tg * 2;
                float cn0 = CNs[col0], cn1 = CNs[col0 + 1];
                candChk(acc[mi][ni][0], xn[s0], cn0, best[s0], rl0,     col0,     LD, LP, s_cnt, rowBase);
                candChk(acc[mi][ni][1], xn[s0], cn1, best[s0], rl0,     col0 + 1, LD, LP, s_cnt, rowBase);
                candChk(acc[mi][ni][2], xn[s1], cn0, best[s1], rl0 + 8, col0,     LD, LP, s_cnt, rowBase);
                candChk(acc[mi][ni][3], xn[s1], cn1, best[s1], rl0 + 8, col0 + 1, LD, LP, s_cnt, rowBase);
            }
        }
        // quad tighten
#pragma unroll
        for (int s = 0; s < 4; s++) {
            best[s] = fminf(best[s], __shfl_xor_sync(0xffffffffu, best[s], 1));
            best[s] = fminf(best[s], __shfl_xor_sync(0xffffffffu, best[s], 2));
        }
    }

    // per-row final approx best
    __syncthreads();
    if (wn == 0 && tg == 0) {
#pragma unroll
        for (int s = 0; s < 4; s++) {
            int rl = wm * 32 + (s >> 1) * 16 + (s & 1) * 8 + g;
            FBs[rl] = best[s];
        }
    }
    __syncthreads();
    if (wn == 1 && tg == 0) {
#pragma unroll
        for (int s = 0; s < 4; s++) {
            int rl = wm * 32 + (s >> 1) * 16 + (s & 1) * 8 + g;
            FBs[rl] = fminf(FBs[rl], best[s]);
        }
    }
    __syncthreads();

    // filter candidates vs final best (FL reuses B smem)
    const int n = min(*s_cnt, LCAP);
    for (int i = tid; i < n; i += 256) {
        unsigned p = LP[i];
        if (LD[i] <= FBs[p >> 10] + THR) {
            int o = atomicAdd(s_out, 1);
            unsigned e = ((unsigned)rowBase << 10) + p;  // (rowBase+rl)<<10 | col
            if (o < FCAP) FL[o] = e;
            else {
                int gi = atomicAdd(&g_candCount, 1);
                if (gi < GCAP) g_cand[gi] = e;
            }
        }
    }
    __syncthreads();
    if (tid == 0) *s_gb = atomicAdd(&g_candCount, min(*s_out, FCAP));
    __syncthreads();
    const int m = min(*s_out, FCAP), gb = *s_gb;
    for (int i = tid; i < m; i += 256)
        if (gb + i < GCAP) g_cand[gb + i] = FL[i];
}

// ---------------------------------------------------------------------------
// Exact refine: one warp per candidate; lane 0 replays the reference-exact
// sequential fmaf chain; atomicMin on (distBits<<16 | col) -> first-index min.
// ---------------------------------------------------------------------------
__global__ void __launch_bounds__(256)
vq_refine(const float* __restrict__ X, const float* __restrict__ W)
{
    __shared__ float buf[8][512];
    const int warp = threadIdx.x >> 5, lane = threadIdx.x & 31;
    const int wg = blockIdx.x * 8 + warp;
    const int nw = gridDim.x * 8;
    const int count = min(g_candCount, GCAP);
    for (int e = wg; e < count; e += nw) {
        unsigned ent = g_cand[e];
        int row = ent >> 10, col = ent & 1023;
#pragma unroll
        for (int j = 0; j < 8; j++) {
            buf[warp][lane + j * 32]       = __ldg(X + (size_t)row * DIM + lane + j * 32);
            buf[warp][256 + lane + j * 32] = __ldg(W + (size_t)col * DIM + lane + j * 32);
        }
        __syncwarp();
        if (lane == 0) {
            float acc = 0.f;
#pragma unroll 8
            for (int k = 0; k < DIM; k++)
                acc = fmaf(buf[warp][k], buf[warp][256 + k], acc);
            float t = __fadd_rn(g_rowNorm[row], g_codeNorm[col]);
            float d = __fadd_rn(t, -2.0f * acc);
            unsigned long long key =
                (((unsigned long long)__float_as_uint(d)) << 16) | (unsigned)col;
            atomicMin(&g_key[row], key);
        }
        __syncwarp();
    }
}

// ---------------------------------------------------------------------------
__global__ void vq_quant(const float* __restrict__ inp, const float* __restrict__ wt,
                         float* __restrict__ out)
{
    __shared__ float bsum[8];
    const int warp = threadIdx.x >> 5, lane = threadIdx.x & 31;
    const int row = blockIdx.x * 8 + warp;
    const int idx = (int)(g_key[row] & 0xFFFFull);

    const float4* x = (const float4*)(inp + (size_t)row * DIM);
    const float4* w = (const float4*)(wt + (size_t)idx * DIM);
    float4* oi = (float4*)(out + (size_t)row * DIM);
    float4* oq = (float4*)(out + OFF_QUANT + (size_t)row * DIM);
    float4* oe = (float4*)(out + OFF_ENC + (size_t)row * KCODES);

    float s = 0.f;
#pragma unroll
    for (int t = 0; t < 2; t++) {
        int p = lane + t * 32;
        float4 xv = __ldg(x + p);
        float4 wv = __ldg(w + p);
        oi[p] = xv;
        float4 qs;
        qs.x = __fadd_rn(xv.x, __fadd_rn(wv.x, -xv.x));
        qs.y = __fadd_rn(xv.y, __fadd_rn(wv.y, -xv.y));
        qs.z = __fadd_rn(xv.z, __fadd_rn(wv.z, -xv.z));
        qs.w = __fadd_rn(xv.w, __fadd_rn(wv.w, -xv.w));
        oq[p] = qs;
        float dx = wv.x - xv.x, dy = wv.y - xv.y;
        float dz = wv.z - xv.z, dw = wv.w - xv.w;
        s += dx * dx + dy * dy + dz * dz + dw * dw;
    }
#pragma unroll
    for (int t = 0; t < 8; t++) {
        int p = lane + t * 32;
        int base = p * 4;
        float4 v = make_float4(0.f, 0.f, 0.f, 0.f);
        int d = idx - base;
        if (d >= 0 && d < 4) {
            if (d == 0) v.x = 1.f; else if (d == 1) v.y = 1.f;
            else if (d == 2) v.z = 1.f; else v.w = 1.f;
        }
        oe[p] = v;
    }
#pragma unroll
    for (int o = 16; o > 0; o >>= 1) s += __shfl_xor_sync(0xffffffffu, s, o);
    if (lane == 0) { bsum[warp] = s; atomicAdd(&g_counts[idx], 1); }
    __syncthreads();
    if (threadIdx.x == 0) {
        float t = bsum[0] + bsum[1] + bsum[2] + bsum[3]
                + bsum[4] + bsum[5] + bsum[6] + bsum[7];
        atomicAdd(&g_lossSum, t);
    }
}

__global__ void vq_final(float* __restrict__ out)
{
    __shared__ float red[1024];
    int t = threadIdx.x;
    float p = (float)g_counts[t] * (1.0f / (float)N_VEC);
    red[t] = p * logf(p + 1e-10f);
    __syncthreads();
    for (int o = 512; o > 0; o >>= 1) {
        if (t < o) red[t] += red[t + o];
        __syncthreads();
    }
    if (t == 0) {
        float loss = g_lossSum * (1.0f / (float)(N_VEC * DIM));
        out[OFF_QLOSS]     = loss;
        out[OFF_QLOSS + 1] = loss;
        out[OFF_QLOSS + 2] = expf(-red[0]);
    }
}

// ---------------------------------------------------------------------------
extern "C" void kernel_launch(void* const* d_in, const int* in_sizes, int n_in,
                              void* d_out, int out_size)
{
    const float* inp = (const float*)d_in[0];
    const float* wt  = (const float*)d_in[1];
    if (n_in >= 2 && in_sizes[0] == KCODES * DIM && in_sizes[1] == N_VEC * DIM) {
        const float* tmp = inp; inp = wt; wt = tmp;
    }
    float* out = (float*)d_out;

    static bool attrDone = false;
    if (!attrDone) {
        (void)cudaFuncSetAttribute(vq_mma, cudaFuncAttributeMaxDynamicSharedMemorySize,
                                   SM_TOTAL);
        attrDone = true;
    }

    vq_init<<<KCODES / 8, 256>>>(wt);
    vq_rownorm<<<N_VEC / 8, 256>>>(inp);
    vq_mma<<<N_VEC / BM, 256, SM_TOTAL>>>(inp, wt);
    vq_refine<<<296, 256>>>(inp, wt);
    vq_quant<<<N_VEC / 8, 256>>>(inp, wt, out);
    vq_final<<<1, 1024>>>(out);
}

// round 6
// speedup vs baseline: 1.7438x; 1.1677x over previous
#include <cuda_runtime.h>
#include <math.h>
#include <stdint.h>

#define N_VEC  32768
#define DIM    256
#define KCODES 1024

#define OFF_QUANT  (N_VEC * DIM)
#define OFF_ENC    (2 * N_VEC * DIM)
#define OFF_QLOSS  (2 * N_VEC * DIM + N_VEC * KCODES)

#define THR 2e-4f

// mma tiling
#define BM 128
#define BN 128
#define BK 32
#define NCHUNKS (KCODES / BN)   // 8
#define LDAS 260                // A smem row stride (floats)
#define LDBS 36                 // B smem col stride (floats)
#define LCAP 8192               // smem candidate list entries
#define GCAP (1 << 22)          // global candidate cap

// smem byte offsets
#define SO_A   0
#define SO_B   133120                    // 128*260*4
#define SO_CN  (SO_B + 18432)            // B: 128*36*4
#define SO_FB  (SO_CN + 4096)
#define SO_RC  (SO_FB + 512)
#define SO_LD  (SO_RC + 512)
#define SO_LP  (SO_LD + LCAP * 4)
#define SO_CNT (SO_LP + LCAP * 4)
#define SM_TOTAL (SO_CNT + 64)           // 222336 B < 227 KB

__device__ float g_codeNorm[KCODES];
__device__ float g_rowNorm[N_VEC];
__device__ unsigned long long g_key[N_VEC];
__device__ int   g_counts[KCODES];
__device__ float g_lossSum;
__device__ int   g_candCount;
__device__ unsigned int g_cand[GCAP];

// ---------------------------------------------------------------------------
__device__ __forceinline__ float tf32_rn(float x) {
    uint32_t u;
    asm("cvt.rna.tf32.f32 %0, %1;" : "=r"(u) : "f"(x));
    return __uint_as_float(u);
}

__device__ __forceinline__ void mma_tf32(float* c, const uint32_t* a,
                                         uint32_t b0, uint32_t b1) {
    asm volatile(
        "mma.sync.aligned.m16n8k8.row.col.f32.tf32.tf32.f32 "
        "{%0,%1,%2,%3}, {%4,%5,%6,%7}, {%8,%9}, {%0,%1,%2,%3};"
        : "+f"(c[0]), "+f"(c[1]), "+f"(c[2]), "+f"(c[3])
        : "r"(a[0]), "r"(a[1]), "r"(a[2]), "r"(a[3]), "r"(b0), "r"(b1));
}

// ---------------------------------------------------------------------------
__global__ void vq_init(const float* __restrict__ w)
{
    const int warp = threadIdx.x >> 5, lane = threadIdx.x & 31;
    const int code = blockIdx.x * 8 + warp;
    const float* wr = w + (size_t)code * DIM;
    float s = 0.f;
#pragma unroll
    for (int i = 0; i < 8; i++) { float v = wr[lane + i * 32]; s = fmaf(v, v, s); }
#pragma unroll
    for (int o = 16; o > 0; o >>= 1) s += __shfl_xor_sync(0xffffffffu, s, o);
    if (lane == 0) g_codeNorm[code] = s;
    if (blockIdx.x == 0) {
        for (int i = threadIdx.x; i < KCODES; i += 256) g_counts[i] = 0;
        if (threadIdx.x == 0) { g_lossSum = 0.f; g_candCount = 0; }
    }
}

__global__ void vq_rownorm(const float* __restrict__ inp)
{
    const int warp = threadIdx.x >> 5, lane = threadIdx.x & 31;
    const int row = blockIdx.x * 8 + warp;
    const float* xr = inp + (size_t)row * DIM;
    float s = 0.f;
#pragma unroll
    for (int i = 0; i < 8; i++) { float v = xr[lane + i * 32]; s = fmaf(v, v, s); }
#pragma unroll
    for (int o = 16; o > 0; o >>= 1) s += __shfl_xor_sync(0xffffffffu, s, o);
    if (lane == 0) { g_rowNorm[row] = s; g_key[row] = 0xFFFFFFFFFFFFFFFFull; }
}

// ---------------------------------------------------------------------------
extern __shared__ char dynsmem[];

__device__ __forceinline__ void candChk(float a, float xnv, float cn, float& best,
                                        int rl, int col, float* LD, unsigned* LP,
                                        int* s_cnt, int rowBase)
{
    float t = __fadd_rn(xnv, cn);
    float d = __fadd_rn(t, -2.0f * a);
    if (d <= best + THR) {
        if (d < best) best = d;
        int i = atomicAdd(s_cnt, 1);
        if (i < LCAP) { LD[i] = d; LP[i] = ((unsigned)rl << 10) | (unsigned)col; }
        else {
            int gi = atomicAdd(&g_candCount, 1);
            if (gi < GCAP)
                g_cand[gi] = ((unsigned)(rowBase + rl) << 10) | (unsigned)col;
        }
    }
}

__global__ void __launch_bounds__(256, 1)
vq_mma(const float* __restrict__ X, const float* __restrict__ W)
{
    float*    As  = (float*)(dynsmem + SO_A);
    float*    Bs  = (float*)(dynsmem + SO_B);
    float*    CNs = (float*)(dynsmem + SO_CN);
    float*    FBs = (float*)(dynsmem + SO_FB);
    int*      RC  = (int*)(dynsmem + SO_RC);
    float*    LD  = (float*)(dynsmem + SO_LD);
    unsigned* LP  = (unsigned*)(dynsmem + SO_LP);
    int*      s_cnt = (int*)(dynsmem + SO_CNT);

    const int tid = threadIdx.x;
    const int warp = tid >> 5, lane = tid & 31;
    const int wm = warp >> 1, wn = warp & 1;
    const int g = lane >> 2, tg = lane & 3;
    const int rowBase = blockIdx.x * BM;

    if (tid == 0) *s_cnt = 0;
    if (tid < BM) RC[tid] = 0;

    // A tile: load + tf32 convert, [row][k] stride LDAS
#pragma unroll
    for (int j = 0; j < 32; j++) {
        int l4 = tid + j * 256;
        int row = l4 >> 6, c4 = l4 & 63;
        float4 v = __ldg((const float4*)(X + (size_t)(rowBase + row) * DIM + c4 * 4));
        float4 t;
        t.x = tf32_rn(v.x); t.y = tf32_rn(v.y);
        t.z = tf32_rn(v.z); t.w = tf32_rn(v.w);
        *(float4*)(As + row * LDAS + c4 * 4) = t;
    }
#pragma unroll
    for (int j = 0; j < 4; j++) CNs[tid + j * 256] = g_codeNorm[tid + j * 256];

    float xn[4], best[4];
#pragma unroll
    for (int s = 0; s < 4; s++) {
        int rl = wm * 32 + (s >> 1) * 16 + (s & 1) * 8 + g;
        xn[s] = g_rowNorm[rowBase + rl];
        best[s] = 3.4e38f;
    }
    __syncthreads();

    for (int c = 0; c < NCHUNKS; c++) {
        const int colBase = c * BN;
        float acc[2][8][4];
#pragma unroll
        for (int mi = 0; mi < 2; mi++)
#pragma unroll
            for (int ni = 0; ni < 8; ni++)
#pragma unroll
                for (int q = 0; q < 4; q++) acc[mi][ni][q] = 0.f;

        float4 pre[4];
#pragma unroll
        for (int j = 0; j < 4; j++) {
            int lin = tid + j * 256;
            int col = lin >> 3, kq = lin & 7;
            pre[j] = __ldg((const float4*)(W + (size_t)(colBase + col) * DIM + kq * 4));
        }
        __syncthreads();
#pragma unroll
        for (int j = 0; j < 4; j++) {
            int lin = tid + j * 256;
            int col = lin >> 3, kq = lin & 7;
            float4 v = pre[j], t;
            t.x = tf32_rn(v.x); t.y = tf32_rn(v.y);
            t.z = tf32_rn(v.z); t.w = tf32_rn(v.w);
            *(float4*)(Bs + col * LDBS + kq * 4) = t;
        }
        __syncthreads();

        for (int ks = 0; ks < DIM / BK; ks++) {
            if (ks < DIM / BK - 1) {
#pragma unroll
                for (int j = 0; j < 4; j++) {
                    int lin = tid + j * 256;
                    int col = lin >> 3, kq = lin & 7;
                    pre[j] = __ldg((const float4*)(W + (size_t)(colBase + col) * DIM
                                                   + (ks + 1) * BK + kq * 4));
                }
            }
#pragma unroll
            for (int k8 = 0; k8 < 4; k8++) {
                const int ka = ks * BK + k8 * 8 + tg;
                const int kb = k8 * 8 + tg;
                uint32_t aF[2][4];
#pragma unroll
                for (int mi = 0; mi < 2; mi++) {
                    const float* ap = As + (wm * 32 + mi * 16 + g) * LDAS;
                    aF[mi][0] = __float_as_uint(ap[ka]);
                    aF[mi][1] = __float_as_uint(ap[8 * LDAS + ka]);
                    aF[mi][2] = __float_as_uint(ap[ka + 4]);
                    aF[mi][3] = __float_as_uint(ap[8 * LDAS + ka + 4]);
                }
#pragma unroll
                for (int ni = 0; ni < 8; ni++) {
                    const float* bp = Bs + (wn * 64 + ni * 8 + g) * LDBS;
                    uint32_t b0 = __float_as_uint(bp[kb]);
                    uint32_t b1 = __float_as_uint(bp[kb + 4]);
                    mma_tf32(acc[0][ni], aF[0], b0, b1);
                    mma_tf32(acc[1][ni], aF[1], b0, b1);
                }
            }
            if (ks < DIM / BK - 1) {
                __syncthreads();
#pragma unroll
                for (int j = 0; j < 4; j++) {
                    int lin = tid + j * 256;
                    int col = lin >> 3, kq = lin & 7;
                    float4 v = pre[j], t;
                    t.x = tf32_rn(v.x); t.y = tf32_rn(v.y);
                    t.z = tf32_rn(v.z); t.w = tf32_rn(v.w);
                    *(float4*)(Bs + col * LDBS + kq * 4) = t;
                }
                __syncthreads();
            }
        }

        // distance epilogue + candidate appends
#pragma unroll
        for (int mi = 0; mi < 2; mi++) {
            const int rl0 = wm * 32 + mi * 16 + g;
            const int s0 = mi * 2, s1 = mi * 2 + 1;
#pragma unroll
            for (int ni = 0; ni < 8; ni++) {
                int col0 = colBase + wn * 64 + ni * 8 + tg * 2;
                float cn0 = CNs[col0], cn1 = CNs[col0 + 1];
                candChk(acc[mi][ni][0], xn[s0], cn0, best[s0], rl0,     col0,     LD, LP, s_cnt, rowBase);
                candChk(acc[mi][ni][1], xn[s0], cn1, best[s0], rl0,     col0 + 1, LD, LP, s_cnt, rowBase);
                candChk(acc[mi][ni][2], xn[s1], cn0, best[s1], rl0 + 8, col0,     LD, LP, s_cnt, rowBase);
                candChk(acc[mi][ni][3], xn[s1], cn1, best[s1], rl0 + 8, col0 + 1, LD, LP, s_cnt, rowBase);
            }
        }
        // quad tighten
#pragma unroll
        for (int s = 0; s < 4; s++) {
            best[s] = fminf(best[s], __shfl_xor_sync(0xffffffffu, best[s], 1));
            best[s] = fminf(best[s], __shfl_xor_sync(0xffffffffu, best[s], 2));
        }
    }

    // per-row final approx best
    __syncthreads();
    if (wn == 0 && tg == 0) {
#pragma unroll
        for (int s = 0; s < 4; s++) {
            int rl = wm * 32 + (s >> 1) * 16 + (s & 1) * 8 + g;
            FBs[rl] = best[s];
        }
    }
    __syncthreads();
    if (wn == 1 && tg == 0) {
#pragma unroll
        for (int s = 0; s < 4; s++) {
            int rl = wm * 32 + (s >> 1) * 16 + (s & 1) * 8 + g;
            FBs[rl] = fminf(FBs[rl], best[s]);
        }
    }
    __syncthreads();

    // Pass 1: count survivors per row.
    const int n = min(*s_cnt, LCAP);
    const bool ovf = (*s_cnt > LCAP);
    for (int i = tid; i < n; i += 256) {
        unsigned p = LP[i];
        int rl = p >> 10;
        if (LD[i] <= FBs[rl] + THR) atomicAdd(&RC[rl], 1);
    }
    __syncthreads();
    // Pass 2: single-survivor rows resolved directly; multi rows -> global list.
    for (int i = tid; i < n; i += 256) {
        unsigned p = LP[i];
        int rl = p >> 10;
        if (LD[i] <= FBs[rl] + THR) {
            unsigned col = p & 1023u;
            if (!ovf && RC[rl] == 1) {
                g_key[rowBase + rl] = (unsigned long long)col;  // exact argmin
            } else {
                int gi = atomicAdd(&g_candCount, 1);
                if (gi < GCAP)
                    g_cand[gi] = ((unsigned)(rowBase + rl) << 10) | col;
            }
        }
    }
}

// ---------------------------------------------------------------------------
// Exact refine for multi-survivor rows only: one warp per candidate; lane 0
// replays the reference-exact sequential fmaf chain; atomicMin on
// (distBits<<16 | col) -> exact first-index argmin.
// ---------------------------------------------------------------------------
__global__ void __launch_bounds__(256)
vq_refine(const float* __restrict__ X, const float* __restrict__ W)
{
    __shared__ float buf[8][512];
    const int warp = threadIdx.x >> 5, lane = threadIdx.x & 31;
    const int wg = blockIdx.x * 8 + warp;
    const int nw = gridDim.x * 8;
    const int count = min(g_candCount, GCAP);
    for (int e = wg; e < count; e += nw) {
        unsigned ent = g_cand[e];
        int row = ent >> 10, col = ent & 1023;
#pragma unroll
        for (int j = 0; j < 8; j++) {
            buf[warp][lane + j * 32]       = __ldg(X + (size_t)row * DIM + lane + j * 32);
            buf[warp][256 + lane + j * 32] = __ldg(W + (size_t)col * DIM + lane + j * 32);
        }
        __syncwarp();
        if (lane == 0) {
            float acc = 0.f;
#pragma unroll 8
            for (int k = 0; k < DIM; k++)
                acc = fmaf(buf[warp][k], buf[warp][256 + k], acc);
            float t = __fadd_rn(g_rowNorm[row], g_codeNorm[col]);
            float d = __fadd_rn(t, -2.0f * acc);
            unsigned long long key =
                (((unsigned long long)__float_as_uint(d)) << 16) | (unsigned)col;
            atomicMin(&g_key[row], key);
        }
        __syncwarp();
    }
}

// ---------------------------------------------------------------------------
__global__ void vq_quant(const float* __restrict__ inp, const float* __restrict__ wt,
                         float* __restrict__ out)
{
    __shared__ float bsum[8];
    const int warp = threadIdx.x >> 5, lane = threadIdx.x & 31;
    const int row = blockIdx.x * 8 + warp;
    const int idx = (int)(g_key[row] & 0xFFFFull);

    const float4* x = (const float4*)(inp + (size_t)row * DIM);
    const float4* w = (const float4*)(wt + (size_t)idx * DIM);
    float4* oi = (float4*)(out + (size_t)row * DIM);
    float4* oq = (float4*)(out + OFF_QUANT + (size_t)row * DIM);
    float4* oe = (float4*)(out + OFF_ENC + (size_t)row * KCODES);

    float s = 0.f;
#pragma unroll
    for (int t = 0; t < 2; t++) {
        int p = lane + t * 32;
        float4 xv = __ldg(x + p);
        float4 wv = __ldg(w + p);
        oi[p] = xv;
        float4 qs;
        qs.x = __fadd_rn(xv.x, __fadd_rn(wv.x, -xv.x));
        qs.y = __fadd_rn(xv.y, __fadd_rn(wv.y, -xv.y));
        qs.z = __fadd_rn(xv.z, __fadd_rn(wv.z, -xv.z));
        qs.w = __fadd_rn(xv.w, __fadd_rn(wv.w, -xv.w));
        oq[p] = qs;
        float dx = wv.x - xv.x, dy = wv.y - xv.y;
        float dz = wv.z - xv.z, dw = wv.w - xv.w;
        s += dx * dx + dy * dy + dz * dz + dw * dw;
    }
#pragma unroll
    for (int t = 0; t < 8; t++) {
        int p = lane + t * 32;
        int base = p * 4;
        float4 v = make_float4(0.f, 0.f, 0.f, 0.f);
        int d = idx - base;
        if (d >= 0 && d < 4) {
            if (d == 0) v.x = 1.f; else if (d == 1) v.y = 1.f;
            else if (d == 2) v.z = 1.f; else v.w = 1.f;
        }
        oe[p] = v;
    }
#pragma unroll
    for (int o = 16; o > 0; o >>= 1) s += __shfl_xor_sync(0xffffffffu, s, o);
    if (lane == 0) { bsum[warp] = s; atomicAdd(&g_counts[idx], 1); }
    __syncthreads();
    if (threadIdx.x == 0) {
        float t = bsum[0] + bsum[1] + bsum[2] + bsum[3]
                + bsum[4] + bsum[5] + bsum[6] + bsum[7];
        atomicAdd(&g_lossSum, t);
    }
}

__global__ void vq_final(float* __restrict__ out)
{
    __shared__ float red[1024];
    int t = threadIdx.x;
    float p = (float)g_counts[t] * (1.0f / (float)N_VEC);
    red[t] = p * logf(p + 1e-10f);
    __syncthreads();
    for (int o = 512; o > 0; o >>= 1) {
        if (t < o) red[t] += red[t + o];
        __syncthreads();
    }
    if (t == 0) {
        float loss = g_lossSum * (1.0f / (float)(N_VEC * DIM));
        out[OFF_QLOSS]     = loss;
        out[OFF_QLOSS + 1] = loss;
        out[OFF_QLOSS + 2] = expf(-red[0]);
    }
}

// ---------------------------------------------------------------------------
extern "C" void kernel_launch(void* const* d_in, const int* in_sizes, int n_in,
                              void* d_out, int out_size)
{
    const float* inp = (const float*)d_in[0];
    const float* wt  = (const float*)d_in[1];
    if (n_in >= 2 && in_sizes[0] == KCODES * DIM && in_sizes[1] == N_VEC * DIM) {
        const float* tmp = inp; inp = wt; wt = tmp;
    }
    float* out = (float*)d_out;

    static bool attrDone = false;
    if (!attrDone) {
        (void)cudaFuncSetAttribute(vq_mma, cudaFuncAttributeMaxDynamicSharedMemorySize,
                                   SM_TOTAL);
        attrDone = true;
    }

    vq_init<<<KCODES / 8, 256>>>(wt);
    vq_rownorm<<<N_VEC / 8, 256>>>(inp);
    vq_mma<<<N_VEC / BM, 256, SM_TOTAL>>>(inp, wt);
    vq_refine<<<148, 256>>>(inp, wt);
    vq_quant<<<N_VEC / 8, 256>>>(inp, wt, out);
    vq_final<<<1, 1024>>>(out);
}